// round 14
// baseline (speedup 1.0000x reference)
#include <cuda_runtime.h>
#include <cuda_bf16.h>
#include <math.h>
#include <cstdint>

#define Bv 64
#define Tv 512
#define Hv 512
#define FH 2048   /* 4*H */

#define NCTA 128
#define NTHR 512

typedef unsigned long long ull;

// ---------------- device scratch ---------------------------------------------
__device__ float g_xproj[Bv * Tv * FH];            // x-projection for current layer
__device__ __nv_bfloat16 g_xhi[Bv * Tv * Hv];      // GEMM A operand, hi part
__device__ __nv_bfloat16 g_xlo[Bv * Tv * Hv];      // GEMM A operand, lo part
__device__ __nv_bfloat16 g_w0hi[FH * Hv];          // W_x0^T [n][k] hi
__device__ __nv_bfloat16 g_w0lo[FH * Hv];
__device__ __nv_bfloat16 g_w1hi[FH * Hv];          // W_x1^T [n][k] hi
__device__ __nv_bfloat16 g_w1lo[FH * Hv];
__device__ __nv_bfloat16 g_wh0hi[FH * Hv];         // W_h0^T [n][k] hi/lo
__device__ __nv_bfloat16 g_wh0lo[FH * Hv];
__device__ __nv_bfloat16 g_wh1hi[FH * Hv];
__device__ __nv_bfloat16 g_wh1lo[FH * Hv];
__device__ __nv_bfloat16 g_hrhi[2][Bv * Hv];       // recurrent h [b][k], hi/lo, dbl-buf
__device__ __nv_bfloat16 g_hrlo[2][Bv * Hv];
__device__ ull g_sg[4][4 * 32];                    // init barrier: arrival ctrs
__device__ ull g_rt[4 * 32];
__device__ ull g_gen2[4 * 32];
__device__ ull g_cnt[4][4 * 32];                   // [bg][block q*32] publish counters

// ---------------- helpers -----------------------------------------------------
__device__ __forceinline__ uint32_t smem_u32(const void* p) {
    uint32_t a;
    asm("{ .reg .u64 t; cvta.to.shared.u64 t, %1; cvt.u32.u64 %0, t; }" : "=r"(a) : "l"(p));
    return a;
}
__device__ __forceinline__ void cp16(uint32_t dst, const void* src) {
    asm volatile("cp.async.cg.shared.global [%0], [%1], 16;" :: "r"(dst), "l"(src) : "memory");
}
#define CP_COMMIT() asm volatile("cp.async.commit_group;" ::: "memory")
#define CP_WAIT0()  asm volatile("cp.async.wait_group 0;" ::: "memory")
#define CP_WAIT1()  asm volatile("cp.async.wait_group 1;" ::: "memory")

__device__ __forceinline__ void ldsm_x4(uint32_t& r0, uint32_t& r1, uint32_t& r2,
                                        uint32_t& r3, uint32_t addr) {
    asm volatile("ldmatrix.sync.aligned.m8n8.x4.shared.b16 {%0,%1,%2,%3}, [%4];"
                 : "=r"(r0), "=r"(r1), "=r"(r2), "=r"(r3) : "r"(addr));
}
__device__ __forceinline__ void mma16816(float* d, const uint32_t* a, const uint32_t* b) {
    asm volatile(
        "mma.sync.aligned.m16n8k16.row.col.f32.bf16.bf16.f32 "
        "{%0,%1,%2,%3}, {%4,%5,%6,%7}, {%8,%9}, {%0,%1,%2,%3};"
        : "+f"(d[0]), "+f"(d[1]), "+f"(d[2]), "+f"(d[3])
        : "r"(a[0]), "r"(a[1]), "r"(a[2]), "r"(a[3]), "r"(b[0]), "r"(b[1]));
}

// fast gates: MUFU-based, rel err ~1e-6
__device__ __forceinline__ float fast_sigmoid(float z) {
    return __fdividef(1.f, 1.f + __expf(-z));
}
__device__ __forceinline__ float fast_tanh(float z) {
    return 1.f - __fdividef(2.f, 1.f + __expf(2.f * z));
}

__device__ __forceinline__ ull ld_acq(const ull* p) {
    ull v;
    asm volatile("ld.acquire.gpu.u64 %0, [%1];" : "=l"(v) : "l"(p) : "memory");
    return v;
}
__device__ __forceinline__ void red_rel_add(ull* p, ull v) {
    asm volatile("red.add.release.gpu.u64 [%0], %1;" :: "l"(p), "l"(v) : "memory");
}

// ---------------- batch-group-local barrier (init only) ----------------------
__device__ __forceinline__ void bg_barrier(int bg, int sg) {
    __syncthreads();
    if (threadIdx.x == 0) {
        ull o;
        asm volatile("atom.add.acq_rel.gpu.u64 %0, [%1], 1;"
                     : "=l"(o) : "l"(&g_sg[bg][sg * 32]) : "memory");
        ull gen = o >> 3;
        if ((o & 7ULL) == 7ULL) {
            ull r;
            asm volatile("atom.add.acq_rel.gpu.u64 %0, [%1], 1;"
                         : "=l"(r) : "l"(&g_rt[bg * 32]) : "memory");
            if ((r & 3ULL) == 3ULL) {
                asm volatile("st.release.gpu.u64 [%0], %1;"
                             :: "l"(&g_gen2[bg * 32]), "l"((r >> 2) + 1ULL) : "memory");
            }
        }
        ull cur;
        do {
            asm volatile("ld.acquire.gpu.u64 %0, [%1];"
                         : "=l"(cur) : "l"(&g_gen2[bg * 32]) : "memory");
        } while (cur <= gen);
    }
    __syncthreads();
}

// ---------------- conversion kernels -----------------------------------------
__global__ void convert_x_kernel(const float* __restrict__ x) {
    const int N2 = Bv * Tv * Hv / 2;
    for (int i = blockIdx.x * blockDim.x + threadIdx.x; i < N2; i += gridDim.x * blockDim.x) {
        float2 v = ((const float2*)x)[i];
        __nv_bfloat16 h0 = __float2bfloat16(v.x);
        __nv_bfloat16 h1 = __float2bfloat16(v.y);
        ((__nv_bfloat162*)g_xhi)[i] = __halves2bfloat162(h0, h1);
        ((__nv_bfloat162*)g_xlo)[i] = __halves2bfloat162(
            __float2bfloat16(v.x - __bfloat162float(h0)),
            __float2bfloat16(v.y - __bfloat162float(h1)));
    }
}

__global__ void convert_w2_kernel(const float* __restrict__ Wx,
                                  const float* __restrict__ Wh,
                                  __nv_bfloat16* __restrict__ xhi,
                                  __nv_bfloat16* __restrict__ xlo,
                                  __nv_bfloat16* __restrict__ hhi,
                                  __nv_bfloat16* __restrict__ hlo) {
    const int total = Hv * FH;
    for (int i = blockIdx.x * blockDim.x + threadIdx.x; i < 2 * total;
         i += gridDim.x * blockDim.x) {
        const float* W = (i < total) ? Wx : Wh;
        __nv_bfloat16* hi = (i < total) ? xhi : hhi;
        __nv_bfloat16* lo = (i < total) ? xlo : hlo;
        int j = (i < total) ? i : i - total;
        int k = j >> 11, n = j & (FH - 1);
        float v = W[j];
        __nv_bfloat16 h = __float2bfloat16(v);
        hi[n * Hv + k] = h;
        lo[n * Hv + k] = __float2bfloat16(v - __bfloat162float(h));
    }
}

// ---------------- mma.sync split-bf16 GEMM (3-stage cp.async pipeline) -------
#define AST 72
#define GBUFB (128 * AST * 2)

__global__ __launch_bounds__(256, 2)
void gemm_mma_kernel(const __nv_bfloat16* __restrict__ whi,
                     const __nv_bfloat16* __restrict__ wlo)
{
    extern __shared__ __nv_bfloat16 smb[];
    const int tid = threadIdx.x;
    const int wid = tid >> 5, lane = tid & 31;
    const int bn = blockIdx.x;
    const int bm = blockIdx.y;
    const int wr = wid >> 2;
    const int wc = wid & 3;

    const uint32_t As0 = smem_u32(smb);
    const uint32_t Bs0 = As0 + 3 * GBUFB;

    float acc[4][4][4];
#pragma unroll
    for (int mi = 0; mi < 4; ++mi)
#pragma unroll
        for (int nj = 0; nj < 4; ++nj)
#pragma unroll
            for (int r = 0; r < 4; ++r) acc[mi][nj][r] = 0.f;

    uint32_t a_base[4], b_base[2];
    {
        int arow = (lane & 15);
        int akof = (lane >> 4) * 8;
#pragma unroll
        for (int mi = 0; mi < 4; ++mi)
            a_base[mi] = As0 + ((wr * 64 + mi * 16 + arow) * AST + akof) * 2;
        int brow = (lane & 7) + ((lane >> 4) & 1) * 8;
        int bkof = ((lane >> 3) & 1) * 8;
#pragma unroll
        for (int np = 0; np < 2; ++np)
            b_base[np] = Bs0 + ((wc * 32 + np * 16 + brow) * AST + bkof) * 2;
    }

    const int sr = tid >> 1;
    const int sh = (tid & 1) * 32;

    auto do_stage = [&](int c, int buf) {
        int p = c >> 3, kc = (c & 7) * 64;
        const __nv_bfloat16* Ag = ((p == 2) ? g_xlo : g_xhi) + (size_t)bm * 128 * Hv;
        const __nv_bfloat16* Bg = ((p == 1) ? wlo : whi) + (size_t)bn * 128 * Hv;
#pragma unroll
        for (int u = 0; u < 4; ++u) {
            int co = sh + u * 8;
            cp16(As0 + buf * GBUFB + (sr * AST + co) * 2, Ag + (size_t)sr * Hv + kc + co);
            cp16(Bs0 + buf * GBUFB + (sr * AST + co) * 2, Bg + (size_t)sr * Hv + kc + co);
        }
        CP_COMMIT();
    };

    do_stage(0, 0);
    do_stage(1, 1);
    for (int c = 0; c < 24; ++c) {
        if (c + 1 < 24) CP_WAIT1(); else CP_WAIT0();
        __syncthreads();
        uint32_t bo = (uint32_t)(c % 3) * GBUFB;
#pragma unroll
        for (int ks = 0; ks < 4; ++ks) {
            uint32_t a[4][4], b[2][4];
#pragma unroll
            for (int mi = 0; mi < 4; ++mi)
                ldsm_x4(a[mi][0], a[mi][1], a[mi][2], a[mi][3], a_base[mi] + bo + ks * 32);
#pragma unroll
            for (int np = 0; np < 2; ++np)
                ldsm_x4(b[np][0], b[np][1], b[np][2], b[np][3], b_base[np] + bo + ks * 32);
#pragma unroll
            for (int mi = 0; mi < 4; ++mi) {
#pragma unroll
                for (int nj = 0; nj < 4; ++nj) {
                    uint32_t bf[2] = { b[nj >> 1][(nj & 1) * 2],
                                       b[nj >> 1][(nj & 1) * 2 + 1] };
                    mma16816(acc[mi][nj], a[mi], bf);
                }
            }
        }
        if (c + 2 < 24) do_stage(c + 2, (c + 2) % 3);
    }

    const int erow = lane >> 2;
    const int ecol = (lane & 3) * 2;
#pragma unroll
    for (int mi = 0; mi < 4; ++mi) {
#pragma unroll
        for (int nj = 0; nj < 4; ++nj) {
            int row0 = bm * 128 + wr * 64 + mi * 16 + erow;
            int col  = bn * 128 + wc * 32 + nj * 8 + ecol;
            *(float2*)&g_xproj[(size_t)row0 * FH + col] =
                make_float2(acc[mi][nj][0], acc[mi][nj][1]);
            *(float2*)&g_xproj[(size_t)(row0 + 8) * FH + col] =
                make_float2(acc[mi][nj][2], acc[mi][nj][3]);
        }
    }
}

// ---------------- persistent recurrent LSTM layer (tensor-core) --------------
// Barrier-free exchange with per-(bg, k-block) counters. This round:
//  - lane0-only acquire polling (+__syncwarp) -> 32x less L2 poll traffic
//  - per-epilogue-warp red.add.release publish (64 arrivals/block/step) issued
//    right after each warp's own h stores -> publish leaves the critical path
#define WRS 520
#define WBUF (64 * WRS * 2)
#define HBUF (16 * WRS * 2)
#define OFF_H 133120
#define OFF_Z (OFF_H + 2 * HBUF)
#define LSTM_SMEM (OFF_Z + 4 * 64 * 20 * 4 + 1024)

__global__ __launch_bounds__(NTHR, 1)
void lstm_layer_kernel(const __nv_bfloat16* __restrict__ whT_hi,
                       const __nv_bfloat16* __restrict__ whT_lo,
                       const float* __restrict__ bvec,
                       const float* __restrict__ h_in,
                       const float* __restrict__ c_in,
                       float* __restrict__ seq_out_ext, int seq_to_internal,
                       float* __restrict__ hT_out,
                       float* __restrict__ cT_out)
{
    extern __shared__ float smemf[];
    const uint32_t sb = smem_u32(smemf);
    const uint32_t Wb = sb;                 // W hi at +0, lo at +WBUF
    const uint32_t Hb = sb + OFF_H;         // h hi at +0, lo at +HBUF
    float* z_s = smemf + OFF_Z / 4;         // 4 copies of [64][20]

    const float* xp = g_xproj;
    const int tid = threadIdx.x;
    const int cg = blockIdx.x & 31;
    const int bg = blockIdx.x >> 5;
    const int sg = cg >> 3;                 // this CTA's publish block
    const int n0 = cg * 16;
    const int bb0 = bg * 16;

    // ---- stage W slice (64 rows x 512 k, hi+lo) via cp.async, once ----
    for (int f = tid; f < 8192; f += NTHR) {
        int buf = f >> 12;
        int rem = f & 4095;
        int c = rem >> 6;
        int off = rem & 63;
        const __nv_bfloat16* src = (buf ? whT_lo : whT_hi)
            + ((size_t)((c >> 4) * Hv + n0 + (c & 15)) << 9) + off * 8;
        cp16(Wb + buf * WBUF + c * (WRS * 2) + off * 16, src);
    }
    CP_COMMIT();

    const int eb = tid >> 4, ej = tid & 15;

    // ---- c seed (register) + h seed (bf16 hi/lo, [b][k] layout) ----
    float c_reg = 0.f;
    if (tid < 256) {
        c_reg = c_in[(bb0 + eb) * Hv + n0 + ej];
        float v = h_in[(bb0 + eb) * Hv + n0 + ej];
        __nv_bfloat16 hh = __float2bfloat16(v);
        int gi = (bb0 + eb) * Hv + n0 + ej;
        g_hrhi[0][gi] = hh;
        g_hrlo[0][gi] = __float2bfloat16(v - __bfloat162float(hh));
    }
    const float bgi = bvec[0] + bvec[1];
    const float bgf = bvec[2] + bvec[3];
    const float bgg = bvec[4] + bvec[5];
    const float bgo = bvec[6] + bvec[7];

    // seed publish: h(-1) available; 8 arrivals per CTA keeps step arithmetic
    __syncthreads();
    if (tid == 0) red_rel_add(&g_cnt[bg][sg * 32], 8ULL);
    CP_WAIT0();
    bg_barrier(bg, sg);   // all seeds in; snapshot counter bases

    const int wid = tid >> 5, lane = tid & 31;
    const int mi = wid & 3;                // m-tile (16 z-cols)
    const int kh = wid >> 2;               // k-quarter / block id (128 k)

    const ull cnt_base = ld_acq(&g_cnt[bg][kh * 32]);

    const uint32_t a_rel = (uint32_t)(((mi * 16 + (lane & 15)) * WRS
                                       + kh * 128 + (lane >> 4) * 8) * 2);
    const uint32_t b_rel = (uint32_t)(((((lane & 7) + ((lane >> 4) & 1) * 8)) * WRS
                                       + kh * 128 + ((lane >> 3) & 1) * 8) * 2);

    const int ii = (wid & 3) * 32 + lane;  // 0..127 within the 4-warp block group

    float pend_h = 0.f;   // deferred sequence-output value (step t-1)

    for (int t = 0; t < Tv; ++t) {
        const __nv_bfloat16* shi = g_hrhi[t & 1];
        const __nv_bfloat16* slo = g_hrlo[t & 1];
        const int dst = (t & 1) ^ 1;

        // prefetch x-projection (independent of exchange)
        float x0, x1, x2, x3;
        if (tid < 256) {
            int xbase = ((bb0 + eb) * Tv + t) * FH + n0 + ej;
            x0 = xp[xbase];
            x1 = xp[xbase + Hv];
            x2 = xp[xbase + 2 * Hv];
            x3 = xp[xbase + 3 * Hv];
            // deferred sequence-output store for step t-1 (off critical path)
            if (t > 0) {
                size_t o = (size_t)((bb0 + eb) * Tv + (t - 1)) * Hv + n0 + ej;
                if (seq_to_internal) {
                    __nv_bfloat16 hh = __float2bfloat16(pend_h);
                    g_xhi[o] = hh;
                    g_xlo[o] = __float2bfloat16(pend_h - __bfloat162float(hh));
                } else {
                    seq_out_ext[o] = pend_h;
                }
            }
        }

        // ---- wait for MY k-block's 64 producer-warp arrivals (lane0 poll) ---
        {
            const ull target = cnt_base + 64ULL * (ull)t;
            if (lane == 0) {
                ull cur;
                do { cur = ld_acq(&g_cnt[bg][kh * 32]); } while (cur < target);
            }
            __syncwarp();
        }
#pragma unroll
        for (int u = 0; u < 2; ++u) {
            int f = ii * 2 + u;            // 0..255
            int row = f >> 4, off = f & 15;
            cp16(Hb + row * (WRS * 2) + kh * 256 + off * 16,
                 shi + ((size_t)(bb0 + row) << 9) + kh * 128 + off * 8);
        }
        CP_COMMIT();
#pragma unroll
        for (int u = 0; u < 2; ++u) {
            int f = ii * 2 + u;
            int row = f >> 4, off = f & 15;
            cp16(Hb + HBUF + row * (WRS * 2) + kh * 256 + off * 16,
                 slo + ((size_t)(bb0 + row) << 9) + kh * 128 + off * 8);
        }
        CP_COMMIT();

        float acc[2][4], acc2[2][4];
#pragma unroll
        for (int nj = 0; nj < 2; ++nj)
#pragma unroll
            for (int r = 0; r < 4; ++r) { acc[nj][r] = 0.f; acc2[nj][r] = 0.f; }

        // fused passes 0+1: (W_hi + W_lo) x h_hi; dual accumulators
        CP_WAIT1();
        asm volatile("bar.sync %0, %1;" :: "r"(1 + kh), "r"(128) : "memory");
#pragma unroll
        for (int ks = 0; ks < 8; ++ks) {
            float* d0 = (ks & 1) ? acc2[0] : acc[0];
            float* d1 = (ks & 1) ? acc2[1] : acc[1];
            uint32_t b[4], a0[4], a1[4];
            ldsm_x4(b[0], b[1], b[2], b[3], Hb + b_rel + ks * 32);
            ldsm_x4(a0[0], a0[1], a0[2], a0[3], Wb + a_rel + ks * 32);
            mma16816(d0, a0, b);
            mma16816(d1, a0, b + 2);
            ldsm_x4(a1[0], a1[1], a1[2], a1[3], Wb + WBUF + a_rel + ks * 32);
            mma16816(d0, a1, b);
            mma16816(d1, a1, b + 2);
        }
        // pass 2: W_hi x h_lo
        CP_WAIT0();
        asm volatile("bar.sync %0, %1;" :: "r"(1 + kh), "r"(128) : "memory");
#pragma unroll
        for (int ks = 0; ks < 8; ++ks) {
            float* d0 = (ks & 1) ? acc2[0] : acc[0];
            float* d1 = (ks & 1) ? acc2[1] : acc[1];
            uint32_t a[4], b[4];
            ldsm_x4(a[0], a[1], a[2], a[3], Wb + a_rel + ks * 32);
            ldsm_x4(b[0], b[1], b[2], b[3], Hb + HBUF + b_rel + ks * 32);
            mma16816(d0, a, b);
            mma16816(d1, a, b + 2);
        }
#pragma unroll
        for (int nj = 0; nj < 2; ++nj)
#pragma unroll
            for (int r = 0; r < 4; ++r) acc[nj][r] += acc2[nj][r];

        // write z fragments
        {
            int r = lane >> 2, cp2 = (lane & 3) * 2;
            float* zk = z_s + kh * 1280;
#pragma unroll
            for (int nj = 0; nj < 2; ++nj) {
                int b = nj * 8 + cp2;
                *(float2*)&zk[(mi * 16 + r) * 20 + b] =
                    make_float2(acc[nj][0], acc[nj][1]);
                *(float2*)&zk[(mi * 16 + r + 8) * 20 + b] =
                    make_float2(acc[nj][2], acc[nj][3]);
            }
        }
        __syncthreads();

        // gate epilogue: each epilogue warp publishes as soon as ITS h stores
        // are issued (syncwarp orders lanes' stores before lane0's release)
        if (tid < 256) {
            float zi = x0 + bgi, zf = x1 + bgf, zg = x2 + bgg, zo = x3 + bgo;
#pragma unroll
            for (int q = 0; q < 4; ++q) {
                const float* zk = z_s + q * 1280;
                zi += zk[(0  + ej) * 20 + eb];
                zf += zk[(16 + ej) * 20 + eb];
                zg += zk[(32 + ej) * 20 + eb];
                zo += zk[(48 + ej) * 20 + eb];
            }
            float ig = fast_sigmoid(zi);
            float fg = fast_sigmoid(zf);
            float gg = fast_tanh(zg);
            float og = fast_sigmoid(zo);
            float cn = fmaf(fg, c_reg, ig * gg);
            c_reg = cn;
            float hn = og * fast_tanh(cn);
            __nv_bfloat16 hh = __float2bfloat16(hn);
            __nv_bfloat16 hl = __float2bfloat16(hn - __bfloat162float(hh));
            int gi = (bb0 + eb) * Hv + n0 + ej;
            g_hrhi[dst][gi] = hh;
            g_hrlo[dst][gi] = hl;
            __syncwarp();
            if (lane == 0) red_rel_add(&g_cnt[bg][sg * 32], 1ULL);  // publish
            pend_h = hn;
            if (t == Tv - 1) {
                size_t o = (size_t)((bb0 + eb) * Tv + t) * Hv + n0 + ej;
                if (seq_to_internal) {
                    g_xhi[o] = hh;
                    g_xlo[o] = hl;
                } else {
                    seq_out_ext[o] = hn;
                }
                hT_out[(bb0 + eb) * Hv + n0 + ej] = hn;
                cT_out[(bb0 + eb) * Hv + n0 + ej] = cn;
            }
        }
        __syncthreads();                      // protect z_s for next step
    }
}

// ---------------- launch -----------------------------------------------------
extern "C" void kernel_launch(void* const* d_in, const int* in_sizes, int n_in,
                              void* d_out, int out_size)
{
    const float* x   = (const float*)d_in[0];
    const float* h   = (const float*)d_in[1];
    const float* c   = (const float*)d_in[2];
    const float* Wx0 = (const float*)d_in[3];
    const float* Wh0 = (const float*)d_in[4];
    const float* b0  = (const float*)d_in[5];
    const float* Wx1 = (const float*)d_in[6];
    const float* Wh1 = (const float*)d_in[7];
    const float* b1  = (const float*)d_in[8];
    float* out = (float*)d_out;

    cudaFuncSetAttribute(lstm_layer_kernel,
                         cudaFuncAttributeMaxDynamicSharedMemorySize, LSTM_SMEM);
    const int GEMM_SMEM = 6 * GBUFB;   // 110592
    cudaFuncSetAttribute(gemm_mma_kernel,
                         cudaFuncAttributeMaxDynamicSharedMemorySize, GEMM_SMEM);

    float* out1 = out;
    float* newh = out + (size_t)Bv * Tv * Hv;
    float* newc = newh + 2 * Bv * Hv;

    __nv_bfloat16 *w0hi, *w0lo, *w1hi, *w1lo, *wh0hi, *wh0lo, *wh1hi, *wh1lo;
    cudaGetSymbolAddress((void**)&w0hi, g_w0hi);
    cudaGetSymbolAddress((void**)&w0lo, g_w0lo);
    cudaGetSymbolAddress((void**)&w1hi, g_w1hi);
    cudaGetSymbolAddress((void**)&w1lo, g_w1lo);
    cudaGetSymbolAddress((void**)&wh0hi, g_wh0hi);
    cudaGetSymbolAddress((void**)&wh0lo, g_wh0lo);
    cudaGetSymbolAddress((void**)&wh1hi, g_wh1hi);
    cudaGetSymbolAddress((void**)&wh1lo, g_wh1lo);

    dim3 gg(FH / 128, (Bv * Tv) / 128);   // (16, 256)

    convert_x_kernel<<<4096, 256>>>(x);                              // 0
    convert_w2_kernel<<<1024, 256>>>(Wx0, Wh0, w0hi, w0lo, wh0hi, wh0lo); // 1
    gemm_mma_kernel<<<gg, 256, GEMM_SMEM>>>(w0hi, w0lo);             // 2
    lstm_layer_kernel<<<NCTA, NTHR, LSTM_SMEM>>>(                    // 3
        wh0hi, wh0lo, b0, h, c, nullptr, 1, newh, newc);

    convert_w2_kernel<<<1024, 256>>>(Wx1, Wh1, w1hi, w1lo, wh1hi, wh1lo); // 4
    gemm_mma_kernel<<<gg, 256, GEMM_SMEM>>>(w1hi, w1lo);             // 5
    lstm_layer_kernel<<<NCTA, NTHR, LSTM_SMEM>>>(                    // 6
        wh1hi, wh1lo, b1, h + Bv * Hv, c + Bv * Hv, out1, 0,
        newh + Bv * Hv, newc + Bv * Hv);
}

// round 15
// speedup vs baseline: 1.0392x; 1.0392x over previous
#include <cuda_runtime.h>
#include <cuda_bf16.h>
#include <math.h>
#include <cstdint>

#define Bv 64
#define Tv 512
#define Hv 512
#define FH 2048   /* 4*H */

#define NCTA 128
#define NTHR 512

typedef unsigned long long ull;

// ---------------- device scratch ---------------------------------------------
__device__ float g_xproj[Bv * Tv * FH];            // x-projection for current layer
__device__ __nv_bfloat16 g_xhi[Bv * Tv * Hv];      // GEMM A operand, hi part
__device__ __nv_bfloat16 g_xlo[Bv * Tv * Hv];      // GEMM A operand, lo part
__device__ __nv_bfloat16 g_w0hi[FH * Hv];          // W_x0^T [n][k] hi
__device__ __nv_bfloat16 g_w0lo[FH * Hv];
__device__ __nv_bfloat16 g_w1hi[FH * Hv];          // W_x1^T [n][k] hi
__device__ __nv_bfloat16 g_w1lo[FH * Hv];
__device__ __nv_bfloat16 g_wh0hi[FH * Hv];         // W_h0^T [n][k] hi/lo
__device__ __nv_bfloat16 g_wh0lo[FH * Hv];
__device__ __nv_bfloat16 g_wh1hi[FH * Hv];
__device__ __nv_bfloat16 g_wh1lo[FH * Hv];
__device__ __nv_bfloat16 g_hrhi[2][Bv * Hv];       // recurrent h [b][k], hi/lo, dbl-buf
__device__ __nv_bfloat16 g_hrlo[2][Bv * Hv];
__device__ ull g_sg[4][4 * 32];                    // init barrier: arrival ctrs
__device__ ull g_rt[4 * 32];
__device__ ull g_gen2[4 * 32];
__device__ ull g_cnt[4][4 * 32];                   // [bg][block q*32] publish counters

// ---------------- helpers -----------------------------------------------------
__device__ __forceinline__ uint32_t smem_u32(const void* p) {
    uint32_t a;
    asm("{ .reg .u64 t; cvta.to.shared.u64 t, %1; cvt.u32.u64 %0, t; }" : "=r"(a) : "l"(p));
    return a;
}
__device__ __forceinline__ void cp16(uint32_t dst, const void* src) {
    asm volatile("cp.async.cg.shared.global [%0], [%1], 16;" :: "r"(dst), "l"(src) : "memory");
}
#define CP_COMMIT() asm volatile("cp.async.commit_group;" ::: "memory")
#define CP_WAIT0()  asm volatile("cp.async.wait_group 0;" ::: "memory")
#define CP_WAIT1()  asm volatile("cp.async.wait_group 1;" ::: "memory")

__device__ __forceinline__ void ldsm_x4(uint32_t& r0, uint32_t& r1, uint32_t& r2,
                                        uint32_t& r3, uint32_t addr) {
    asm volatile("ldmatrix.sync.aligned.m8n8.x4.shared.b16 {%0,%1,%2,%3}, [%4];"
                 : "=r"(r0), "=r"(r1), "=r"(r2), "=r"(r3) : "r"(addr));
}
__device__ __forceinline__ void mma16816(float* d, const uint32_t* a, const uint32_t* b) {
    asm volatile(
        "mma.sync.aligned.m16n8k16.row.col.f32.bf16.bf16.f32 "
        "{%0,%1,%2,%3}, {%4,%5,%6,%7}, {%8,%9}, {%0,%1,%2,%3};"
        : "+f"(d[0]), "+f"(d[1]), "+f"(d[2]), "+f"(d[3])
        : "r"(a[0]), "r"(a[1]), "r"(a[2]), "r"(a[3]), "r"(b[0]), "r"(b[1]));
}

// fast gates: MUFU-based, rel err ~1e-6
__device__ __forceinline__ float fast_sigmoid(float z) {
    return __fdividef(1.f, 1.f + __expf(-z));
}
__device__ __forceinline__ float fast_tanh(float z) {
    return 1.f - __fdividef(2.f, 1.f + __expf(2.f * z));
}

__device__ __forceinline__ ull ld_acq(const ull* p) {
    ull v;
    asm volatile("ld.acquire.gpu.u64 %0, [%1];" : "=l"(v) : "l"(p) : "memory");
    return v;
}
__device__ __forceinline__ void red_rel_add(ull* p, ull v) {
    asm volatile("red.add.release.gpu.u64 [%0], %1;" :: "l"(p), "l"(v) : "memory");
}

// ---------------- batch-group-local barrier (init only) ----------------------
__device__ __forceinline__ void bg_barrier(int bg, int sg) {
    __syncthreads();
    if (threadIdx.x == 0) {
        ull o;
        asm volatile("atom.add.acq_rel.gpu.u64 %0, [%1], 1;"
                     : "=l"(o) : "l"(&g_sg[bg][sg * 32]) : "memory");
        ull gen = o >> 3;
        if ((o & 7ULL) == 7ULL) {
            ull r;
            asm volatile("atom.add.acq_rel.gpu.u64 %0, [%1], 1;"
                         : "=l"(r) : "l"(&g_rt[bg * 32]) : "memory");
            if ((r & 3ULL) == 3ULL) {
                asm volatile("st.release.gpu.u64 [%0], %1;"
                             :: "l"(&g_gen2[bg * 32]), "l"((r >> 2) + 1ULL) : "memory");
            }
        }
        ull cur;
        do {
            asm volatile("ld.acquire.gpu.u64 %0, [%1];"
                         : "=l"(cur) : "l"(&g_gen2[bg * 32]) : "memory");
        } while (cur <= gen);
    }
    __syncthreads();
}

// ---------------- conversion kernels -----------------------------------------
__global__ void convert_x_kernel(const float* __restrict__ x) {
    const int N2 = Bv * Tv * Hv / 2;
    for (int i = blockIdx.x * blockDim.x + threadIdx.x; i < N2; i += gridDim.x * blockDim.x) {
        float2 v = ((const float2*)x)[i];
        __nv_bfloat16 h0 = __float2bfloat16(v.x);
        __nv_bfloat16 h1 = __float2bfloat16(v.y);
        ((__nv_bfloat162*)g_xhi)[i] = __halves2bfloat162(h0, h1);
        ((__nv_bfloat162*)g_xlo)[i] = __halves2bfloat162(
            __float2bfloat16(v.x - __bfloat162float(h0)),
            __float2bfloat16(v.y - __bfloat162float(h1)));
    }
}

__global__ void convert_w2_kernel(const float* __restrict__ Wx,
                                  const float* __restrict__ Wh,
                                  __nv_bfloat16* __restrict__ xhi,
                                  __nv_bfloat16* __restrict__ xlo,
                                  __nv_bfloat16* __restrict__ hhi,
                                  __nv_bfloat16* __restrict__ hlo) {
    const int total = Hv * FH;
    for (int i = blockIdx.x * blockDim.x + threadIdx.x; i < 2 * total;
         i += gridDim.x * blockDim.x) {
        const float* W = (i < total) ? Wx : Wh;
        __nv_bfloat16* hi = (i < total) ? xhi : hhi;
        __nv_bfloat16* lo = (i < total) ? xlo : hlo;
        int j = (i < total) ? i : i - total;
        int k = j >> 11, n = j & (FH - 1);
        float v = W[j];
        __nv_bfloat16 h = __float2bfloat16(v);
        hi[n * Hv + k] = h;
        lo[n * Hv + k] = __float2bfloat16(v - __bfloat162float(h));
    }
}

// ---------------- mma.sync split-bf16 GEMM (fused-pass, 2-stage pipeline) ----
// acc = xhi*whi + xhi*wlo + xlo*whi. Phase 1 (8 chunks): stage {xhi,whi,wlo}
// once, run BOTH matmuls (A fragments shared). Phase 2 (8 chunks): {xlo,whi}.
// Staging units 48 -> 40, chunk boundaries 24 -> 16. SMEM unchanged (110KB).
#define AST 72
#define GBUFB (128 * AST * 2)

__global__ __launch_bounds__(256, 2)
void gemm_mma_kernel(const __nv_bfloat16* __restrict__ whi,
                     const __nv_bfloat16* __restrict__ wlo)
{
    extern __shared__ __nv_bfloat16 smb[];
    const int tid = threadIdx.x;
    const int wid = tid >> 5, lane = tid & 31;
    const int bn = blockIdx.x;
    const int bm = blockIdx.y;
    const int wr = wid >> 2;
    const int wc = wid & 3;

    const uint32_t S0 = smem_u32(smb);   // buf(b) slot(s) at S0 + (b*3+s)*GBUFB

    float acc[4][4][4];
#pragma unroll
    for (int mi = 0; mi < 4; ++mi)
#pragma unroll
        for (int nj = 0; nj < 4; ++nj)
#pragma unroll
            for (int r = 0; r < 4; ++r) acc[mi][nj][r] = 0.f;

    uint32_t arel[4], brel[2];
    {
        int arow = (lane & 15);
        int akof = (lane >> 4) * 8;
#pragma unroll
        for (int mi = 0; mi < 4; ++mi)
            arel[mi] = ((wr * 64 + mi * 16 + arow) * AST + akof) * 2;
        int brow = (lane & 7) + ((lane >> 4) & 1) * 8;
        int bkof = ((lane >> 3) & 1) * 8;
#pragma unroll
        for (int np = 0; np < 2; ++np)
            brel[np] = ((wc * 32 + np * 16 + brow) * AST + bkof) * 2;
    }

    const int sr = tid >> 1;
    const int sh = (tid & 1) * 32;

    // stage global chunk g (0..15) into buffer buf
    auto do_stage = [&](int g, int buf) {
        uint32_t B = S0 + (uint32_t)(buf * 3) * GBUFB;
        if (g < 8) {
            int kc = g * 64;
            const __nv_bfloat16* Ag  = g_xhi + (size_t)bm * 128 * Hv;
            const __nv_bfloat16* B0g = whi + (size_t)bn * 128 * Hv;
            const __nv_bfloat16* B1g = wlo + (size_t)bn * 128 * Hv;
#pragma unroll
            for (int u = 0; u < 4; ++u) {
                int co = sh + u * 8;
                uint32_t d = B + (sr * AST + co) * 2;
                cp16(d,             Ag  + (size_t)sr * Hv + kc + co);
                cp16(d + GBUFB,     B0g + (size_t)sr * Hv + kc + co);
                cp16(d + 2 * GBUFB, B1g + (size_t)sr * Hv + kc + co);
            }
        } else {
            int kc = (g - 8) * 64;
            const __nv_bfloat16* Ag  = g_xlo + (size_t)bm * 128 * Hv;
            const __nv_bfloat16* B0g = whi + (size_t)bn * 128 * Hv;
#pragma unroll
            for (int u = 0; u < 4; ++u) {
                int co = sh + u * 8;
                uint32_t d = B + (sr * AST + co) * 2;
                cp16(d,         Ag  + (size_t)sr * Hv + kc + co);
                cp16(d + GBUFB, B0g + (size_t)sr * Hv + kc + co);
            }
        }
        CP_COMMIT();
    };

    do_stage(0, 0);
    for (int g = 0; g < 16; ++g) {
        if (g + 1 < 16) { do_stage(g + 1, (g + 1) & 1); CP_WAIT1(); }
        else            { CP_WAIT0(); }
        __syncthreads();
        uint32_t B = S0 + (uint32_t)((g & 1) * 3) * GBUFB;
        bool two = (g < 8);
#pragma unroll
        for (int ks = 0; ks < 4; ++ks) {
            uint32_t a[4][4], b[2][4];
#pragma unroll
            for (int mi = 0; mi < 4; ++mi)
                ldsm_x4(a[mi][0], a[mi][1], a[mi][2], a[mi][3],
                        B + arel[mi] + ks * 32);
            // B0
#pragma unroll
            for (int np = 0; np < 2; ++np)
                ldsm_x4(b[np][0], b[np][1], b[np][2], b[np][3],
                        B + GBUFB + brel[np] + ks * 32);
#pragma unroll
            for (int mi = 0; mi < 4; ++mi)
#pragma unroll
                for (int nj = 0; nj < 4; ++nj) {
                    uint32_t bf[2] = { b[nj >> 1][(nj & 1) * 2],
                                       b[nj >> 1][(nj & 1) * 2 + 1] };
                    mma16816(acc[mi][nj], a[mi], bf);
                }
            // B1 (phase 1 only), A fragments reused
            if (two) {
#pragma unroll
                for (int np = 0; np < 2; ++np)
                    ldsm_x4(b[np][0], b[np][1], b[np][2], b[np][3],
                            B + 2 * GBUFB + brel[np] + ks * 32);
#pragma unroll
                for (int mi = 0; mi < 4; ++mi)
#pragma unroll
                    for (int nj = 0; nj < 4; ++nj) {
                        uint32_t bf[2] = { b[nj >> 1][(nj & 1) * 2],
                                           b[nj >> 1][(nj & 1) * 2 + 1] };
                        mma16816(acc[mi][nj], a[mi], bf);
                    }
            }
        }
        __syncthreads();
    }

    const int erow = lane >> 2;
    const int ecol = (lane & 3) * 2;
#pragma unroll
    for (int mi = 0; mi < 4; ++mi) {
#pragma unroll
        for (int nj = 0; nj < 4; ++nj) {
            int row0 = bm * 128 + wr * 64 + mi * 16 + erow;
            int col  = bn * 128 + wc * 32 + nj * 8 + ecol;
            *(float2*)&g_xproj[(size_t)row0 * FH + col] =
                make_float2(acc[mi][nj][0], acc[mi][nj][1]);
            *(float2*)&g_xproj[(size_t)(row0 + 8) * FH + col] =
                make_float2(acc[mi][nj][2], acc[mi][nj][3]);
        }
    }
}

// ---------------- persistent recurrent LSTM layer (tensor-core) --------------
// Barrier-free exchange with per-(bg, k-block) counters; lane0-only polling;
// per-epilogue-warp release publish. This round: W fragments for ks=0,1 are
// preloaded ABOVE the cp.async waits (W smem is step-invariant; the wait
// blocks issue, so ptxas cannot hoist these) and reused in pass 2.
#define WRS 520
#define WBUF (64 * WRS * 2)
#define HBUF (16 * WRS * 2)
#define OFF_H 133120
#define OFF_Z (OFF_H + 2 * HBUF)
#define LSTM_SMEM (OFF_Z + 4 * 64 * 20 * 4 + 1024)

__global__ __launch_bounds__(NTHR, 1)
void lstm_layer_kernel(const __nv_bfloat16* __restrict__ whT_hi,
                       const __nv_bfloat16* __restrict__ whT_lo,
                       const float* __restrict__ bvec,
                       const float* __restrict__ h_in,
                       const float* __restrict__ c_in,
                       float* __restrict__ seq_out_ext, int seq_to_internal,
                       float* __restrict__ hT_out,
                       float* __restrict__ cT_out)
{
    extern __shared__ float smemf[];
    const uint32_t sb = smem_u32(smemf);
    const uint32_t Wb = sb;                 // W hi at +0, lo at +WBUF
    const uint32_t Hb = sb + OFF_H;         // h hi at +0, lo at +HBUF
    float* z_s = smemf + OFF_Z / 4;         // 4 copies of [64][20]

    const float* xp = g_xproj;
    const int tid = threadIdx.x;
    const int cg = blockIdx.x & 31;
    const int bg = blockIdx.x >> 5;
    const int sg = cg >> 3;                 // this CTA's publish block
    const int n0 = cg * 16;
    const int bb0 = bg * 16;

    // ---- stage W slice (64 rows x 512 k, hi+lo) via cp.async, once ----
    for (int f = tid; f < 8192; f += NTHR) {
        int buf = f >> 12;
        int rem = f & 4095;
        int c = rem >> 6;
        int off = rem & 63;
        const __nv_bfloat16* src = (buf ? whT_lo : whT_hi)
            + ((size_t)((c >> 4) * Hv + n0 + (c & 15)) << 9) + off * 8;
        cp16(Wb + buf * WBUF + c * (WRS * 2) + off * 16, src);
    }
    CP_COMMIT();

    const int eb = tid >> 4, ej = tid & 15;

    // ---- c seed (register) + h seed (bf16 hi/lo, [b][k] layout) ----
    float c_reg = 0.f;
    if (tid < 256) {
        c_reg = c_in[(bb0 + eb) * Hv + n0 + ej];
        float v = h_in[(bb0 + eb) * Hv + n0 + ej];
        __nv_bfloat16 hh = __float2bfloat16(v);
        int gi = (bb0 + eb) * Hv + n0 + ej;
        g_hrhi[0][gi] = hh;
        g_hrlo[0][gi] = __float2bfloat16(v - __bfloat162float(hh));
    }
    const float bgi = bvec[0] + bvec[1];
    const float bgf = bvec[2] + bvec[3];
    const float bgg = bvec[4] + bvec[5];
    const float bgo = bvec[6] + bvec[7];

    // seed publish: h(-1) available; 8 arrivals per CTA keeps step arithmetic
    __syncthreads();
    if (tid == 0) red_rel_add(&g_cnt[bg][sg * 32], 8ULL);
    CP_WAIT0();
    bg_barrier(bg, sg);   // all seeds in; snapshot counter bases

    const int wid = tid >> 5, lane = tid & 31;
    const int mi = wid & 3;                // m-tile (16 z-cols)
    const int kh = wid >> 2;               // k-quarter / block id (128 k)

    const ull cnt_base = ld_acq(&g_cnt[bg][kh * 32]);

    const uint32_t a_rel = (uint32_t)(((mi * 16 + (lane & 15)) * WRS
                                       + kh * 128 + (lane >> 4) * 8) * 2);
    const uint32_t b_rel = (uint32_t)(((((lane & 7) + ((lane >> 4) & 1) * 8)) * WRS
                                       + kh * 128 + ((lane >> 3) & 1) * 8) * 2);

    const int ii = (wid & 3) * 32 + lane;  // 0..127 within the 4-warp block group

    float pend_h = 0.f;   // deferred sequence-output value (step t-1)

    for (int t = 0; t < Tv; ++t) {
        const __nv_bfloat16* shi = g_hrhi[t & 1];
        const __nv_bfloat16* slo = g_hrlo[t & 1];
        const int dst = (t & 1) ^ 1;

        // prefetch x-projection (independent of exchange)
        float x0, x1, x2, x3;
        if (tid < 256) {
            int xbase = ((bb0 + eb) * Tv + t) * FH + n0 + ej;
            x0 = xp[xbase];
            x1 = xp[xbase + Hv];
            x2 = xp[xbase + 2 * Hv];
            x3 = xp[xbase + 3 * Hv];
            // deferred sequence-output store for step t-1 (off critical path)
            if (t > 0) {
                size_t o = (size_t)((bb0 + eb) * Tv + (t - 1)) * Hv + n0 + ej;
                if (seq_to_internal) {
                    __nv_bfloat16 hh = __float2bfloat16(pend_h);
                    g_xhi[o] = hh;
                    g_xlo[o] = __float2bfloat16(pend_h - __bfloat162float(hh));
                } else {
                    seq_out_ext[o] = pend_h;
                }
            }
        }

        // ---- wait for MY k-block's 64 producer-warp arrivals (lane0 poll) ---
        {
            const ull target = cnt_base + 64ULL * (ull)t;
            if (lane == 0) {
                ull cur;
                do { cur = ld_acq(&g_cnt[bg][kh * 32]); } while (cur < target);
            }
            __syncwarp();
        }
#pragma unroll
        for (int u = 0; u < 2; ++u) {
            int f = ii * 2 + u;            // 0..255
            int row = f >> 4, off = f & 15;
            cp16(Hb + row * (WRS * 2) + kh * 256 + off * 16,
                 shi + ((size_t)(bb0 + row) << 9) + kh * 128 + off * 8);
        }
        CP_COMMIT();
#pragma unroll
        for (int u = 0; u < 2; ++u) {
            int f = ii * 2 + u;
            int row = f >> 4, off = f & 15;
            cp16(Hb + HBUF + row * (WRS * 2) + kh * 256 + off * 16,
                 slo + ((size_t)(bb0 + row) << 9) + kh * 128 + off * 8);
        }
        CP_COMMIT();

        float acc[2][4], acc2[2][4];
#pragma unroll
        for (int nj = 0; nj < 2; ++nj)
#pragma unroll
            for (int r = 0; r < 4; ++r) { acc[nj][r] = 0.f; acc2[nj][r] = 0.f; }

        // preload W fragments for ks=0,1 (step-invariant smem) BEFORE the
        // cp.async wait blocks this warp — shortens the post-wake chain
        uint32_t pa0[2][4], pa1[2][4];
#pragma unroll
        for (int k2 = 0; k2 < 2; ++k2) {
            ldsm_x4(pa0[k2][0], pa0[k2][1], pa0[k2][2], pa0[k2][3],
                    Wb + a_rel + k2 * 32);
            ldsm_x4(pa1[k2][0], pa1[k2][1], pa1[k2][2], pa1[k2][3],
                    Wb + WBUF + a_rel + k2 * 32);
        }

        // fused passes 0+1: (W_hi + W_lo) x h_hi; dual accumulators
        CP_WAIT1();
        asm volatile("bar.sync %0, %1;" :: "r"(1 + kh), "r"(128) : "memory");
#pragma unroll
        for (int ks = 0; ks < 8; ++ks) {
            float* d0 = (ks & 1) ? acc2[0] : acc[0];
            float* d1 = (ks & 1) ? acc2[1] : acc[1];
            uint32_t b[4], a0[4], a1[4];
            ldsm_x4(b[0], b[1], b[2], b[3], Hb + b_rel + ks * 32);
            if (ks < 2) {
#pragma unroll
                for (int r = 0; r < 4; ++r) { a0[r] = pa0[ks][r]; a1[r] = pa1[ks][r]; }
            } else {
                ldsm_x4(a0[0], a0[1], a0[2], a0[3], Wb + a_rel + ks * 32);
                ldsm_x4(a1[0], a1[1], a1[2], a1[3], Wb + WBUF + a_rel + ks * 32);
            }
            mma16816(d0, a0, b);
            mma16816(d1, a0, b + 2);
            mma16816(d0, a1, b);
            mma16816(d1, a1, b + 2);
        }
        // pass 2: W_hi x h_lo (reuse pa0 for ks=0,1)
        CP_WAIT0();
        asm volatile("bar.sync %0, %1;" :: "r"(1 + kh), "r"(128) : "memory");
#pragma unroll
        for (int ks = 0; ks < 8; ++ks) {
            float* d0 = (ks & 1) ? acc2[0] : acc[0];
            float* d1 = (ks & 1) ? acc2[1] : acc[1];
            uint32_t a[4], b[4];
            ldsm_x4(b[0], b[1], b[2], b[3], Hb + HBUF + b_rel + ks * 32);
            if (ks < 2) {
#pragma unroll
                for (int r = 0; r < 4; ++r) a[r] = pa0[ks][r];
            } else {
                ldsm_x4(a[0], a[1], a[2], a[3], Wb + a_rel + ks * 32);
            }
            mma16816(d0, a, b);
            mma16816(d1, a, b + 2);
        }
#pragma unroll
        for (int nj = 0; nj < 2; ++nj)
#pragma unroll
            for (int r = 0; r < 4; ++r) acc[nj][r] += acc2[nj][r];

        // write z fragments
        {
            int r = lane >> 2, cp2 = (lane & 3) * 2;
            float* zk = z_s + kh * 1280;
#pragma unroll
            for (int nj = 0; nj < 2; ++nj) {
                int b = nj * 8 + cp2;
                *(float2*)&zk[(mi * 16 + r) * 20 + b] =
                    make_float2(acc[nj][0], acc[nj][1]);
                *(float2*)&zk[(mi * 16 + r + 8) * 20 + b] =
                    make_float2(acc[nj][2], acc[nj][3]);
            }
        }
        __syncthreads();

        // gate epilogue: each epilogue warp publishes as soon as ITS h stores
        // are issued (syncwarp orders lanes' stores before lane0's release)
        if (tid < 256) {
            float zi = x0 + bgi, zf = x1 + bgf, zg = x2 + bgg, zo = x3 + bgo;
#pragma unroll
            for (int q = 0; q < 4; ++q) {
                const float* zk = z_s + q * 1280;
                zi += zk[(0  + ej) * 20 + eb];
                zf += zk[(16 + ej) * 20 + eb];
                zg += zk[(32 + ej) * 20 + eb];
                zo += zk[(48 + ej) * 20 + eb];
            }
            float ig = fast_sigmoid(zi);
            float fg = fast_sigmoid(zf);
            float gg = fast_tanh(zg);
            float og = fast_sigmoid(zo);
            float cn = fmaf(fg, c_reg, ig * gg);
            c_reg = cn;
            float hn = og * fast_tanh(cn);
            __nv_bfloat16 hh = __float2bfloat16(hn);
            __nv_bfloat16 hl = __float2bfloat16(hn - __bfloat162float(hh));
            int gi = (bb0 + eb) * Hv + n0 + ej;
            g_hrhi[dst][gi] = hh;
            g_hrlo[dst][gi] = hl;
            __syncwarp();
            if (lane == 0) red_rel_add(&g_cnt[bg][sg * 32], 1ULL);  // publish
            pend_h = hn;
            if (t == Tv - 1) {
                size_t o = (size_t)((bb0 + eb) * Tv + t) * Hv + n0 + ej;
                if (seq_to_internal) {
                    g_xhi[o] = hh;
                    g_xlo[o] = hl;
                } else {
                    seq_out_ext[o] = hn;
                }
                hT_out[(bb0 + eb) * Hv + n0 + ej] = hn;
                cT_out[(bb0 + eb) * Hv + n0 + ej] = cn;
            }
        }
        __syncthreads();                      // protect z_s for next step
    }
}

// ---------------- launch -----------------------------------------------------
extern "C" void kernel_launch(void* const* d_in, const int* in_sizes, int n_in,
                              void* d_out, int out_size)
{
    const float* x   = (const float*)d_in[0];
    const float* h   = (const float*)d_in[1];
    const float* c   = (const float*)d_in[2];
    const float* Wx0 = (const float*)d_in[3];
    const float* Wh0 = (const float*)d_in[4];
    const float* b0  = (const float*)d_in[5];
    const float* Wx1 = (const float*)d_in[6];
    const float* Wh1 = (const float*)d_in[7];
    const float* b1  = (const float*)d_in[8];
    float* out = (float*)d_out;

    cudaFuncSetAttribute(lstm_layer_kernel,
                         cudaFuncAttributeMaxDynamicSharedMemorySize, LSTM_SMEM);
    const int GEMM_SMEM = 6 * GBUFB;   // 110592 (2 bufs x 3 slots)
    cudaFuncSetAttribute(gemm_mma_kernel,
                         cudaFuncAttributeMaxDynamicSharedMemorySize, GEMM_SMEM);

    float* out1 = out;
    float* newh = out + (size_t)Bv * Tv * Hv;
    float* newc = newh + 2 * Bv * Hv;

    __nv_bfloat16 *w0hi, *w0lo, *w1hi, *w1lo, *wh0hi, *wh0lo, *wh1hi, *wh1lo;
    cudaGetSymbolAddress((void**)&w0hi, g_w0hi);
    cudaGetSymbolAddress((void**)&w0lo, g_w0lo);
    cudaGetSymbolAddress((void**)&w1hi, g_w1hi);
    cudaGetSymbolAddress((void**)&w1lo, g_w1lo);
    cudaGetSymbolAddress((void**)&wh0hi, g_wh0hi);
    cudaGetSymbolAddress((void**)&wh0lo, g_wh0lo);
    cudaGetSymbolAddress((void**)&wh1hi, g_wh1hi);
    cudaGetSymbolAddress((void**)&wh1lo, g_wh1lo);

    dim3 gg(FH / 128, (Bv * Tv) / 128);   // (16, 256)

    convert_x_kernel<<<4096, 256>>>(x);                              // 0
    convert_w2_kernel<<<1024, 256>>>(Wx0, Wh0, w0hi, w0lo, wh0hi, wh0lo); // 1
    gemm_mma_kernel<<<gg, 256, GEMM_SMEM>>>(w0hi, w0lo);             // 2
    lstm_layer_kernel<<<NCTA, NTHR, LSTM_SMEM>>>(                    // 3
        wh0hi, wh0lo, b0, h, c, nullptr, 1, newh, newc);

    convert_w2_kernel<<<1024, 256>>>(Wx1, Wh1, w1hi, w1lo, wh1hi, wh1lo); // 4
    gemm_mma_kernel<<<gg, 256, GEMM_SMEM>>>(w1hi, w1lo);             // 5
    lstm_layer_kernel<<<NCTA, NTHR, LSTM_SMEM>>>(                    // 6
        wh1hi, wh1lo, b1, h + Bv * Hv, c + Bv * Hv, out1, 0,
        newh + Bv * Hv, newc + Bv * Hv);
}